// round 8
// baseline (speedup 1.0000x reference)
#include <cuda_runtime.h>

// DistMult edge scoring: out[e] = sum_d X[src[e],d] * R[rel[e],d] * X[dst[e],d]
//
// Round 7 resubmit (infra failure, kernel unchanged): R6 structure (batched
// loads first, folded 8-SHFL reduction, int4 index loads) with one more
// occupancy tier:
//  - __launch_bounds__(256, 7): 36-reg cap -> 7 blocks/SM (87.5% theo occ)
//  - peak float4 liveness reduced 9 -> 8 (32 regs) via 8/3/1 load batching;
//    MLP never below ~5, no SHFL or select inside the load stream.

constexpr int XDIM            = 64;
constexpr int LANES           = 16;
constexpr int EDGES_PER_GROUP = 4;
constexpr int BLOCK           = 256;

__device__ __forceinline__ float dot3(float4 a, float4 r, float4 b) {
    return a.x * r.x * b.x
         + a.y * r.y * b.y
         + a.z * r.z * b.z
         + a.w * r.w * b.w;
}

__global__ __launch_bounds__(BLOCK, 7)
void distmult_kernel(const float* __restrict__ X,
                     const float* __restrict__ R,
                     const int*   __restrict__ edge_list,  // [2, E]
                     const int*   __restrict__ edge_type,  // [1, E]
                     float*       __restrict__ out,        // [E]
                     int num_edges)
{
    int gid   = blockIdx.x * BLOCK + threadIdx.x;
    int group = gid >> 4;
    int lane  = gid & (LANES - 1);

    int e0 = group * EDGES_PER_GROUP;

    int4 src, dst, rel;
    if (e0 + 3 < num_edges) {
        // Fast path (always taken when E % 4 == 0): vectorized index loads.
        src = __ldg(reinterpret_cast<const int4*>(edge_list + e0));
        dst = __ldg(reinterpret_cast<const int4*>(edge_list + num_edges + e0));
        rel = __ldg(reinterpret_cast<const int4*>(edge_type + e0));
    } else {
        int c0 = min(e0 + 0, num_edges - 1);
        int c1 = min(e0 + 1, num_edges - 1);
        int c2 = min(e0 + 2, num_edges - 1);
        int c3 = min(e0 + 3, num_edges - 1);
        src = make_int4(__ldg(&edge_list[c0]), __ldg(&edge_list[c1]),
                        __ldg(&edge_list[c2]), __ldg(&edge_list[c3]));
        dst = make_int4(__ldg(&edge_list[num_edges + c0]), __ldg(&edge_list[num_edges + c1]),
                        __ldg(&edge_list[num_edges + c2]), __ldg(&edge_list[num_edges + c3]));
        rel = make_int4(__ldg(&edge_type[c0]), __ldg(&edge_type[c1]),
                        __ldg(&edge_type[c2]), __ldg(&edge_type[c3]));
    }

    const float4* X4 = reinterpret_cast<const float4*>(X);
    const float4* R4 = reinterpret_cast<const float4*>(R);
    const int V4 = XDIM / 4;  // 16 float4 per row

    // ── Batch 1: 8 gathers in flight (edges 0,1 complete; edge 2 partial).
    float4 a0 = __ldg(X4 + src.x * V4 + lane);
    float4 b0 = __ldg(X4 + dst.x * V4 + lane);
    float4 r0 = __ldg(R4 + rel.x * V4 + lane);
    float4 a1 = __ldg(X4 + src.y * V4 + lane);
    float4 b1 = __ldg(X4 + dst.y * V4 + lane);
    float4 r1 = __ldg(R4 + rel.y * V4 + lane);
    float4 a2 = __ldg(X4 + src.z * V4 + lane);
    float4 b2 = __ldg(X4 + dst.z * V4 + lane);

    // Edge-0 dot retires a0/b0/r0 (12 regs) ...
    float s0 = dot3(a0, r0, b0);

    // ── Batch 2: edge-2 remainder + edge 3 partial (back to 8 live).
    float4 r2 = __ldg(R4 + rel.z * V4 + lane);
    float4 a3 = __ldg(X4 + src.w * V4 + lane);
    float4 b3 = __ldg(X4 + dst.w * V4 + lane);

    float s1 = dot3(a1, r1, b1);

    // ── Batch 3: last gather.
    float4 r3 = __ldg(R4 + rel.w * V4 + lane);

    float s2 = dot3(a2, r2, b2);
    float s3 = dot3(a3, r3, b3);

    // ── Folded reduction, strictly after all loads: 8 SHFLs for 4 edges.
    s0 += __shfl_xor_sync(0xFFFFFFFFu, s0, 8);
    s1 += __shfl_xor_sync(0xFFFFFFFFu, s1, 8);
    s2 += __shfl_xor_sync(0xFFFFFFFFu, s2, 8);
    s3 += __shfl_xor_sync(0xFFFFFFFFu, s3, 8);
    float a = (lane & 8) ? s1 : s0;   // edge0 in lanes 0-7, edge1 in 8-15
    float b = (lane & 8) ? s3 : s2;   // edge2 in lanes 0-7, edge3 in 8-15
    a += __shfl_xor_sync(0xFFFFFFFFu, a, 4);
    b += __shfl_xor_sync(0xFFFFFFFFu, b, 4);
    float c = (lane & 4) ? b : a;
    // quads: lanes0-3 -> edge0, 4-7 -> edge2, 8-11 -> edge1, 12-15 -> edge3
    c += __shfl_xor_sync(0xFFFFFFFFu, c, 2);
    c += __shfl_xor_sync(0xFFFFFFFFu, c, 1);

    // lane0 -> e0+0, lane4 -> e0+2, lane8 -> e0+1, lane12 -> e0+3
    if ((lane & 3) == 0) {
        int off = ((lane >> 3) & 1) | (((lane >> 2) & 1) << 1);
        int e = e0 + off;
        if (e < num_edges)
            out[e] = c;
    }
}

extern "C" void kernel_launch(void* const* d_in, const int* in_sizes, int n_in,
                              void* d_out, int out_size)
{
    const float* X  = (const float*)d_in[0];
    const float* R  = (const float*)d_in[1];
    const int* edge_list = (const int*)d_in[2];
    const int* edge_type = (const int*)d_in[3];
    float* out = (float*)d_out;

    int num_edges = in_sizes[3];

    int groups = (num_edges + EDGES_PER_GROUP - 1) / EDGES_PER_GROUP;
    long long total_threads = (long long)groups * LANES;
    int grid = (int)((total_threads + BLOCK - 1) / BLOCK);

    distmult_kernel<<<grid, BLOCK>>>(X, R, edge_list, edge_type, out, num_edges);
}

// round 9
// speedup vs baseline: 1.2643x; 1.2643x over previous
#include <cuda_runtime.h>

// DistMult edge scoring: out[e] = sum_d X[src[e],d] * R[rel[e],d] * X[dst[e],d]
//
// Round 9: 32-reg-tier kernel (64 warps/SM) with minimized overhead work.
//  - One warp = 4 edges = two 16-lane groups x 2 edges (R3's proven
//    32-reg liveness: 6 float4 + 3 int2 indices live at peak).
//  - int2 index loads: 3 LDG.64/warp, both groups in the same cache line
//    -> ~0.75 wf/edge (was 1.5).
//  - Warp-folded reduction: 5 SHFLs per 4 edges; results on lanes
//    0/8/16/24 -> single contiguous 4-lane store (1 wf / 4 edges).
//  - All gathers issued before any SHFL (round-5 lesson).
//  - __launch_bounds__(256, 8) pins the 32-reg / 8-blocks tier.

constexpr int XDIM  = 64;
constexpr int BLOCK = 256;

__device__ __forceinline__ float dot3(float4 a, float4 r, float4 b) {
    return a.x * r.x * b.x
         + a.y * r.y * b.y
         + a.z * r.z * b.z
         + a.w * r.w * b.w;
}

__global__ __launch_bounds__(BLOCK, 8)
void distmult_kernel(const float* __restrict__ X,
                     const float* __restrict__ R,
                     const int*   __restrict__ edge_list,  // [2, E]
                     const int*   __restrict__ edge_type,  // [1, E]
                     float*       __restrict__ out,        // [E]
                     int num_edges)
{
    int gid    = blockIdx.x * BLOCK + threadIdx.x;
    int wl     = gid & 31;          // lane within warp
    int warp   = gid >> 5;
    int e_base = warp * 4;          // 4 edges per warp
    int grp    = wl >> 4;           // 0: lanes 0-15, 1: lanes 16-31
    int lane16 = wl & 15;
    int e      = e_base + grp * 2;  // first edge of this group's pair

    int2 src, dst, rel;
    if (e_base + 3 < num_edges) {
        // Fast path (always taken when E % 4 == 0). e is even -> 8B aligned.
        src = __ldg(reinterpret_cast<const int2*>(edge_list + e));
        dst = __ldg(reinterpret_cast<const int2*>(edge_list + num_edges + e));
        rel = __ldg(reinterpret_cast<const int2*>(edge_type + e));
    } else {
        int c0 = min(e,     num_edges - 1);
        int c1 = min(e + 1, num_edges - 1);
        src = make_int2(__ldg(&edge_list[c0]), __ldg(&edge_list[c1]));
        dst = make_int2(__ldg(&edge_list[num_edges + c0]),
                        __ldg(&edge_list[num_edges + c1]));
        rel = make_int2(__ldg(&edge_type[c0]), __ldg(&edge_type[c1]));
    }

    const float4* X4 = reinterpret_cast<const float4*>(X);
    const float4* R4 = reinterpret_cast<const float4*>(R);
    const int V4 = XDIM / 4;  // 16 float4 per row

    // Six independent LDG.128 in flight per thread before any dependent math.
    float4 a0 = __ldg(X4 + src.x * V4 + lane16);
    float4 b0 = __ldg(X4 + dst.x * V4 + lane16);
    float4 r0 = __ldg(R4 + rel.x * V4 + lane16);
    float4 a1 = __ldg(X4 + src.y * V4 + lane16);
    float4 b1 = __ldg(X4 + dst.y * V4 + lane16);
    float4 r1 = __ldg(R4 + rel.y * V4 + lane16);

    float s0 = dot3(a0, r0, b0);
    float s1 = dot3(a1, r1, b1);

    // Folded reduction: 5 SHFLs for the warp's 4 edges.
    s0 += __shfl_xor_sync(0xFFFFFFFFu, s0, 8);
    s1 += __shfl_xor_sync(0xFFFFFFFFu, s1, 8);
    float t = (wl & 8) ? s1 : s0;   // low half-group: edge e, high: edge e+1
    t += __shfl_xor_sync(0xFFFFFFFFu, t, 4);
    t += __shfl_xor_sync(0xFFFFFFFFu, t, 2);
    t += __shfl_xor_sync(0xFFFFFFFFu, t, 1);

    // wl=0 -> e_base, wl=8 -> e_base+1, wl=16 -> e_base+2, wl=24 -> e_base+3:
    // 4 contiguous scalar stores, one wavefront.
    if ((wl & 7) == 0) {
        int eo = e_base + (wl >> 3);
        if (eo < num_edges)
            out[eo] = t;
    }
}

extern "C" void kernel_launch(void* const* d_in, const int* in_sizes, int n_in,
                              void* d_out, int out_size)
{
    const float* X  = (const float*)d_in[0];
    const float* R  = (const float*)d_in[1];
    const int* edge_list = (const int*)d_in[2];
    const int* edge_type = (const int*)d_in[3];
    float* out = (float*)d_out;

    int num_edges = in_sizes[3];

    int warps = (num_edges + 3) / 4;           // 4 edges per warp
    long long total_threads = (long long)warps * 32;
    int grid = (int)((total_threads + BLOCK - 1) / BLOCK);

    distmult_kernel<<<grid, BLOCK>>>(X, R, edge_list, edge_type, out, num_edges);
}

// round 10
// speedup vs baseline: 1.2650x; 1.0006x over previous
#include <cuda_runtime.h>

// DistMult edge scoring: out[e] = sum_d X[src[e],d] * R[rel[e],d] * X[dst[e],d]
//
// Round 10: 32-reg-tier (64 warps/SM) kernel with R6-level work amortization.
//  - 8-lane groups: 8 lanes x float4 = 128B = exactly one line per load
//    (perfect sectoring preserved, 6 wf/edge gather floor unchanged).
//  - Warp = 4 groups x 2 edges = 8 edges/warp; two rounds of
//    (6 loads -> dot), round-2 loads reuse round-1's registers; ALL
//    shuffles strictly after all loads (R5 lesson).
//  - Peak liveness: 6 float4 + 3 int2 + carried scalar ~ 31 regs -> fits
//    the 32-reg tier honestly (no R8-style spill).
//  - Reduction: 4 warp-wide SHFLs + 1 select for all 8 edges (0.5/edge).
//  - Index: 3 int2 loads/warp (0.375 wf/edge); single contiguous 8-float
//    store from lanes 0,4,...,28 (0.125 wf/edge).

constexpr int XDIM  = 64;
constexpr int BLOCK = 256;

__device__ __forceinline__ float dot3(float4 a, float4 r, float4 b) {
    return a.x * r.x * b.x
         + a.y * r.y * b.y
         + a.z * r.z * b.z
         + a.w * r.w * b.w;
}

__global__ __launch_bounds__(BLOCK, 8)
void distmult_kernel(const float* __restrict__ X,
                     const float* __restrict__ R,
                     const int*   __restrict__ edge_list,  // [2, E]
                     const int*   __restrict__ edge_type,  // [1, E]
                     float*       __restrict__ out,        // [E]
                     int num_edges)
{
    int gid    = blockIdx.x * BLOCK + threadIdx.x;
    int wl     = gid & 31;
    int warp   = gid >> 5;
    int e_base = warp * 8;          // 8 edges per warp
    int grp    = wl >> 3;           // 0..3 (8-lane groups)
    int lane8  = wl & 7;
    int e      = e_base + grp * 2;  // this group's edge pair (even -> 8B aligned)

    int2 src, dst, rel;
    if (e_base + 7 < num_edges) {
        // Fast path (always taken when E % 8 == 0).
        src = __ldg(reinterpret_cast<const int2*>(edge_list + e));
        dst = __ldg(reinterpret_cast<const int2*>(edge_list + num_edges + e));
        rel = __ldg(reinterpret_cast<const int2*>(edge_type + e));
    } else {
        int c0 = min(e,     num_edges - 1);
        int c1 = min(e + 1, num_edges - 1);
        src = make_int2(__ldg(&edge_list[c0]), __ldg(&edge_list[c1]));
        dst = make_int2(__ldg(&edge_list[num_edges + c0]),
                        __ldg(&edge_list[num_edges + c1]));
        rel = make_int2(__ldg(&edge_type[c0]), __ldg(&edge_type[c1]));
    }

    const float4* X4 = reinterpret_cast<const float4*>(X);
    const float4* R4 = reinterpret_cast<const float4*>(R);
    const int V4 = XDIM / 4;  // 16 float4 per row; row = 2 x (8 x float4)

    // ── Round A: edge e. 6 independent LDG.128, each warp-instruction
    //    touches exactly 4 lines (one per group) -> perfect sectoring.
    float sA;
    {
        float4 a0 = __ldg(X4 + src.x * V4     + lane8);
        float4 a1 = __ldg(X4 + src.x * V4 + 8 + lane8);
        float4 b0 = __ldg(X4 + dst.x * V4     + lane8);
        float4 b1 = __ldg(X4 + dst.x * V4 + 8 + lane8);
        float4 r0 = __ldg(R4 + rel.x * V4     + lane8);
        float4 r1 = __ldg(R4 + rel.x * V4 + 8 + lane8);
        sA = dot3(a0, r0, b0) + dot3(a1, r1, b1);
    }

    // ── Round B: edge e+1 (registers reused; no shuffle issued yet).
    float sB;
    {
        float4 a0 = __ldg(X4 + src.y * V4     + lane8);
        float4 a1 = __ldg(X4 + src.y * V4 + 8 + lane8);
        float4 b0 = __ldg(X4 + dst.y * V4     + lane8);
        float4 b1 = __ldg(X4 + dst.y * V4 + 8 + lane8);
        float4 r0 = __ldg(R4 + rel.y * V4     + lane8);
        float4 r1 = __ldg(R4 + rel.y * V4 + 8 + lane8);
        sB = dot3(a0, r0, b0) + dot3(a1, r1, b1);
    }

    // ── Reduction: 4 warp-wide SHFLs for all 8 edges.
    sA += __shfl_xor_sync(0xFFFFFFFFu, sA, 4);
    sB += __shfl_xor_sync(0xFFFFFFFFu, sB, 4);
    float t = (wl & 4) ? sB : sA;   // quad 0 of group: edge e; quad 1: edge e+1
    t += __shfl_xor_sync(0xFFFFFFFFu, t, 2);
    t += __shfl_xor_sync(0xFFFFFFFFu, t, 1);

    // lane 4k holds edge e_base + k  (k = 0..7): one contiguous 32B store.
    if ((wl & 3) == 0) {
        int eo = e_base + (wl >> 2);
        if (eo < num_edges)
            out[eo] = t;
    }
}

extern "C" void kernel_launch(void* const* d_in, const int* in_sizes, int n_in,
                              void* d_out, int out_size)
{
    const float* X  = (const float*)d_in[0];
    const float* R  = (const float*)d_in[1];
    const int* edge_list = (const int*)d_in[2];
    const int* edge_type = (const int*)d_in[3];
    float* out = (float*)d_out;

    int num_edges = in_sizes[3];

    int warps = (num_edges + 7) / 8;           // 8 edges per warp
    long long total_threads = (long long)warps * 32;
    int grid = (int)((total_threads + BLOCK - 1) / BLOCK);

    distmult_kernel<<<grid, BLOCK>>>(X, R, edge_list, edge_type, out, num_edges);
}